// round 14
// baseline (speedup 1.0000x reference)
#include <cuda_runtime.h>
#include <math_constants.h>

// cummax along T for [B, T, H, C] = [16, 512, 64, 128] fp32.
//
// R13 = R12 champion (85.8us) with UNROLL 16 -> 32.
// Final model:
//   - DRAM% saturates ~77% (mixed 50/50 R/W HBM wall); needs >=56 KB/SM
//     in flight AND benefits mildly from more warps/SM (13.8 > 6.9).
//   - Bench = kernel + DVFS gap; gap tracks instruction rate + regs
//     (penalty observed at 140+ regs, absent at <=72).
// R13 rationale: halve loop overhead (16 outer iters), double per-warp
// read/write burst length (less R/W alternation at the MC), regs ~72
// (known-safe), occupancy unchanged (grid-limited 13.8 warps/SM).

#define B_DIM 16
#define T_DIM 512
#define HC_DIM (64 * 128)            // 8192 floats per timestep
#define HC2 (HC_DIM / 2)             // 4096 float2 per timestep
#define UNROLL 32

__global__ __launch_bounds__(64)
void cummax_time_kernel_v2u32(const float2* __restrict__ in, float2* __restrict__ out) {
    const unsigned col2 = blockIdx.x * blockDim.x + threadIdx.x;   // 0..65535, exact

    const unsigned b      = col2 / HC2;
    const unsigned inner2 = col2 % HC2;

    const size_t base = (size_t)b * T_DIM * HC2 + inner2;
    const float2* __restrict__ p = in + base;
    float2* __restrict__       q = out + base;

    float mx = -CUDART_INF_F;
    float my = -CUDART_INF_F;

    // 16 outer iterations; 32 independent LDG.64 front-batched
    // (256 B/thread in flight), 2 independent max chains, 32 STG.64.
    #pragma unroll 1
    for (int tt = 0; tt < T_DIM; tt += UNROLL) {
        float2 v[UNROLL];
        #pragma unroll
        for (int i = 0; i < UNROLL; ++i) {
            v[i] = __ldcs(p + (size_t)i * HC2);      // streaming LDG.64
        }
        #pragma unroll
        for (int i = 0; i < UNROLL; ++i) {
            mx = fmaxf(mx, v[i].x);  v[i].x = mx;
            my = fmaxf(my, v[i].y);  v[i].y = my;
        }
        #pragma unroll
        for (int i = 0; i < UNROLL; ++i) {
            __stcs(q + (size_t)i * HC2, v[i]);       // streaming STG.64
        }
        p += (size_t)UNROLL * HC2;
        q += (size_t)UNROLL * HC2;
    }
}

extern "C" void kernel_launch(void* const* d_in, const int* in_sizes, int n_in,
                              void* d_out, int out_size) {
    const float2* in = (const float2*)d_in[0];
    float2* out = (float2*)d_out;

    const int total_cols2 = B_DIM * HC2;              // 65536
    const int threads = 64;
    const int blocks = total_cols2 / threads;         // 1024 -> 6.92 blocks/SM

    cummax_time_kernel_v2u32<<<blocks, threads>>>(in, out);
}

// round 15
// speedup vs baseline: 1.0050x; 1.0050x over previous
#include <cuda_runtime.h>
#include <math_constants.h>

// cummax along T for [B, T, H, C] = [16, 512, 64, 128] fp32.
//
// R14: float2 x UNROLL=8, double-buffered.
// Model (complete):
//   - DRAM% wants: >=56 KB/SM outstanding, SHORT per-thread batch period
//     (R13 falsified long bursts: 64B period -> 77.2%, 256B -> 74-75%),
//     and more warps/SM.
//   - Bench adds a DVFS gap tracking instruction rate + regs (bad >=140).
// float2x8 alone = 28 KB/SM (67% regime); the double-buffer keeps the next
// 8 LDG.64 outstanding through every max/store phase -> sustained depth of
// the 56 KB class at HALF the period of R12. Regs ~52-60 (safe zone),
// 13.8 warps/SM, 1024 blocks exact.

#define B_DIM 16
#define T_DIM 512
#define HC_DIM (64 * 128)            // 8192 floats per timestep
#define HC2 (HC_DIM / 2)             // 4096 float2 per timestep
#define UNROLL 8
#define NBATCH (T_DIM / UNROLL)      // 64 batches

__device__ __forceinline__ void load8(float2 (&v)[UNROLL], const float2* __restrict__ p) {
    #pragma unroll
    for (int i = 0; i < UNROLL; ++i)
        v[i] = __ldcs(p + (size_t)i * HC2);          // streaming LDG.64
}

__device__ __forceinline__ void scan_store8(float2 (&v)[UNROLL], float2* __restrict__ q,
                                            float& mx, float& my) {
    #pragma unroll
    for (int i = 0; i < UNROLL; ++i) {
        mx = fmaxf(mx, v[i].x);  v[i].x = mx;
        my = fmaxf(my, v[i].y);  v[i].y = my;
    }
    #pragma unroll
    for (int i = 0; i < UNROLL; ++i)
        __stcs(q + (size_t)i * HC2, v[i]);           // streaming STG.64
}

__global__ __launch_bounds__(64)
void cummax_time_kernel_v2p8(const float2* __restrict__ in, float2* __restrict__ out) {
    const unsigned col2 = blockIdx.x * blockDim.x + threadIdx.x;   // 0..65535, exact

    const unsigned b      = col2 / HC2;
    const unsigned inner2 = col2 % HC2;

    const size_t base = (size_t)b * T_DIM * HC2 + inner2;
    const float2* __restrict__ p = in + base;
    float2* __restrict__       q = out + base;

    const size_t S = (size_t)UNROLL * HC2;           // batch stride

    float mx = -CUDART_INF_F;
    float my = -CUDART_INF_F;

    float2 va[UNROLL], vb[UNROLL];

    // Prologue: batch 0 outstanding.
    load8(va, p);  p += S;

    // 31 iterations x 2 batches: every scan/store phase runs with the next
    // batch's 8 loads already issued.
    #pragma unroll 1
    for (int it = 0; it < (NBATCH - 2) / 2; ++it) {
        load8(vb, p);  p += S;
        scan_store8(va, q, mx, my);  q += S;

        load8(va, p);  p += S;
        scan_store8(vb, q, mx, my);  q += S;
    }

    // Epilogue: batches 62, 63.
    load8(vb, p);
    scan_store8(va, q, mx, my);  q += S;
    scan_store8(vb, q, mx, my);
}

extern "C" void kernel_launch(void* const* d_in, const int* in_sizes, int n_in,
                              void* d_out, int out_size) {
    const float2* in = (const float2*)d_in[0];
    float2* out = (float2*)d_out;

    const int total_cols2 = B_DIM * HC2;              // 65536
    const int threads = 64;
    const int blocks = total_cols2 / threads;         // 1024 -> 6.92 blocks/SM

    cummax_time_kernel_v2p8<<<blocks, threads>>>(in, out);
}

// round 16
// speedup vs baseline: 1.0651x; 1.0598x over previous
#include <cuda_runtime.h>
#include <math_constants.h>

// cummax along T for [B, T, H, C] = [16, 512, 64, 128] fp32.
//
// R15 = R12 VERBATIM (bench champion, 85.8us) — reproducibility measurement.
// Rationale (rigor.md: re-bench before claiming a win):
//   - R14 achieved the best true kernel time (76.9us, DRAM 79.6%) but
//     benched 90.1: the bench-vs-ncu gap no longer fits the regs/instr
//     model. ncu's --cache-control all flatters single launches (clean L2
//     absorbs part of the write stream); the replay loop is steady-state.
//   - Seven kernels bench 90-92; only R7/R12 (plain non-pipelined x16)
//     bench ~86. This round determines whether that 4us is signal or noise:
//     reproduce ~86 -> R12-family is the real optimum, keep perturbing it;
//     land >=89 -> noise band +-4us, switch to best-ncu kernel (R14).

#define B_DIM 16
#define T_DIM 512
#define HC_DIM (64 * 128)            // 8192 floats per timestep
#define HC2 (HC_DIM / 2)             // 4096 float2 per timestep
#define UNROLL 16

__global__ __launch_bounds__(64)
void cummax_time_kernel_v2(const float2* __restrict__ in, float2* __restrict__ out) {
    const unsigned col2 = blockIdx.x * blockDim.x + threadIdx.x;   // 0..65535, exact

    const unsigned b      = col2 / HC2;
    const unsigned inner2 = col2 % HC2;

    const size_t base = (size_t)b * T_DIM * HC2 + inner2;
    const float2* __restrict__ p = in + base;
    float2* __restrict__       q = out + base;

    float mx = -CUDART_INF_F;
    float my = -CUDART_INF_F;

    // 32 outer iterations; 16 independent LDG.64 front-batched
    // (128 B/thread in flight), 2 independent max chains, 16 STG.64.
    #pragma unroll 1
    for (int tt = 0; tt < T_DIM; tt += UNROLL) {
        float2 v[UNROLL];
        #pragma unroll
        for (int i = 0; i < UNROLL; ++i) {
            v[i] = __ldcs(p + (size_t)i * HC2);      // streaming LDG.64
        }
        #pragma unroll
        for (int i = 0; i < UNROLL; ++i) {
            mx = fmaxf(mx, v[i].x);  v[i].x = mx;
            my = fmaxf(my, v[i].y);  v[i].y = my;
        }
        #pragma unroll
        for (int i = 0; i < UNROLL; ++i) {
            __stcs(q + (size_t)i * HC2, v[i]);       // streaming STG.64
        }
        p += (size_t)UNROLL * HC2;
        q += (size_t)UNROLL * HC2;
    }
}

extern "C" void kernel_launch(void* const* d_in, const int* in_sizes, int n_in,
                              void* d_out, int out_size) {
    const float2* in = (const float2*)d_in[0];
    float2* out = (float2*)d_out;

    const int total_cols2 = B_DIM * HC2;              // 65536
    const int threads = 64;
    const int blocks = total_cols2 / threads;         // 1024 -> 6.92 blocks/SM

    cummax_time_kernel_v2<<<blocks, threads>>>(in, out);
}

// round 17
// speedup vs baseline: 1.0723x; 1.0068x over previous
#include <cuda_runtime.h>
#include <math_constants.h>

// cummax along T for [B, T, H, C] = [16, 512, 64, 128] fp32.
//
// R16 = R12 champion (85.1/85.8us, reproduced) with ONE perturbation:
// the scan and store loops are fused, so each element is stored right
// after its running max is updated.
// Mechanism (from R13's falsification): finer per-warp R/W interleave at
// the memory controller raises DRAM% (64B-period configs beat 256B ones by
// ~2-3 pts). Fusing turns the 128B tail write burst into 8B-granular
// compute/store alternation, issues stores ~60cyc earlier, and shortens
// v[i] register lifetimes (expect regs 40 -> ~28).
// Everything else is untouched: float2, UNROLL=16, block=64, grid=1024
// (6.92 blocks/SM, 13.8 warps/SM), __ldcs/__stcs streaming hints,
// immediate offsets off incremented base pointers.

#define B_DIM 16
#define T_DIM 512
#define HC_DIM (64 * 128)            // 8192 floats per timestep
#define HC2 (HC_DIM / 2)             // 4096 float2 per timestep
#define UNROLL 16

__global__ __launch_bounds__(64)
void cummax_time_kernel_v2i(const float2* __restrict__ in, float2* __restrict__ out) {
    const unsigned col2 = blockIdx.x * blockDim.x + threadIdx.x;   // 0..65535, exact

    const unsigned b      = col2 / HC2;
    const unsigned inner2 = col2 % HC2;

    const size_t base = (size_t)b * T_DIM * HC2 + inner2;
    const float2* __restrict__ p = in + base;
    float2* __restrict__       q = out + base;

    float mx = -CUDART_INF_F;
    float my = -CUDART_INF_F;

    // 32 outer iterations; 16 independent LDG.64 front-batched (128 B/thread
    // in flight), then a fused max+store chain: STG.64 issued per element.
    #pragma unroll 1
    for (int tt = 0; tt < T_DIM; tt += UNROLL) {
        float2 v[UNROLL];
        #pragma unroll
        for (int i = 0; i < UNROLL; ++i) {
            v[i] = __ldcs(p + (size_t)i * HC2);      // streaming LDG.64
        }
        #pragma unroll
        for (int i = 0; i < UNROLL; ++i) {
            mx = fmaxf(mx, v[i].x);  v[i].x = mx;
            my = fmaxf(my, v[i].y);  v[i].y = my;
            __stcs(q + (size_t)i * HC2, v[i]);       // store immediately
        }
        p += (size_t)UNROLL * HC2;
        q += (size_t)UNROLL * HC2;
    }
}

extern "C" void kernel_launch(void* const* d_in, const int* in_sizes, int n_in,
                              void* d_out, int out_size) {
    const float2* in = (const float2*)d_in[0];
    float2* out = (float2*)d_out;

    const int total_cols2 = B_DIM * HC2;              // 65536
    const int threads = 64;
    const int blocks = total_cols2 / threads;         // 1024 -> 6.92 blocks/SM

    cummax_time_kernel_v2i<<<blocks, threads>>>(in, out);
}